// round 13
// baseline (speedup 1.0000x reference)
// HyperGatedLinear — mma.sync tf32 (sm_103 plain target; tcgen05 unavailable).
// out[b,o] = a·(x·bw^T) + (1-a)·(Y·dwW_view^T) + (1-a)·(x·dwb_view^T)
//          + (1-a)·(z·dbW^T) + a·bb[o] + (1-a)·dbb[o],
// Y[b, i*128+zc] = x[b,i]·z[b,zc]; dw_W viewed [OUT, IN*ZD] is K-major contiguous.
#include <cuda_runtime.h>
#include <cstdint>
#include <math.h>

#define B_DIM    128
#define OUT_DIM  1024
#define THREADS  256
#define STAGES   4
#define A_ST     16384          // 128 m x 32 k fp32, fragment-major
#define B_ST     36864          // 256 n rows x 36 floats (144 B padded)
#define SMEM_TOTAL (STAGES * (A_ST + B_ST))   // 212992 B

__device__ float g_scratch[34][B_DIM * OUT_DIM];

// ---------- helpers ----------
static __device__ __forceinline__ uint32_t smem_u32(const void* p) {
    uint32_t r;
    asm("{ .reg .u64 t; cvta.to.shared.u64 t, %1; cvt.u32.u64 %0, t; }" : "=r"(r) : "l"(p));
    return r;
}
static __device__ __forceinline__ uint32_t rna(float f) {
    uint32_t r; asm("cvt.rna.tf32.f32 %0, %1;" : "=r"(r) : "f"(f)); return r;
}
#define CPA16(dst, src) asm volatile("cp.async.cg.shared.global [%0], [%1], 16;" :: "r"(dst), "l"(src) : "memory")
#define CPA_COMMIT()    asm volatile("cp.async.commit_group;" ::: "memory")
#define CPA_WAIT(n)     asm volatile("cp.async.wait_group %0;" :: "n"(n) : "memory")
#define STS128(a, r0, r1, r2, r3) \
    asm volatile("st.shared.v4.b32 [%0], {%1,%2,%3,%4};" :: "r"(a), "r"(r0), "r"(r1), "r"(r2), "r"(r3) : "memory")
#define LDS128(r0, r1, r2, r3, a) \
    asm volatile("ld.shared.v4.b32 {%0,%1,%2,%3}, [%4];" : "=r"(r0), "=r"(r1), "=r"(r2), "=r"(r3) : "r"(a))
#define LDS32(r, a) asm volatile("ld.shared.b32 %0, [%1];" : "=r"(r) : "r"(a))

#define MMA(c, aa, bb)                                                          \
    asm volatile(                                                               \
        "mma.sync.aligned.m16n8k8.row.col.f32.tf32.tf32.f32 "                   \
        "{%0,%1,%2,%3}, {%4,%5,%6,%7}, {%8,%9}, {%0,%1,%2,%3};"                 \
        : "+f"((c)[0]), "+f"((c)[1]), "+f"((c)[2]), "+f"((c)[3])                \
        : "r"((aa)[0]), "r"((aa)[1]), "r"((aa)[2]), "r"((aa)[3]),               \
          "r"((bb)[0]), "r"((bb)[1]))

// ---------- GEMM kernel: grid (4 N-tiles, 34 K-splits), 256 threads ----------
__global__ void __launch_bounds__(THREADS, 1)
hyper_gemm(const float* __restrict__ x, const float* __restrict__ z,
           const float* __restrict__ base_w, const float* __restrict__ dw_W,
           const float* __restrict__ dw_b, const float* __restrict__ db_W,
           const float* __restrict__ s_ptr)
{
    extern __shared__ char smem[];
    const uint32_t sb = smem_u32(smem);
    const uint32_t aB = sb;
    const uint32_t bB = sb + STAGES * A_ST;

    const int tid  = threadIdx.x;
    const int lane = tid & 31;
    const int q    = tid >> 5;          // warp id 0..7
    const int gid  = lane >> 2;         // 0..7
    const int tig  = lane & 3;          // 0..3
    const int wr   = q >> 2;            // 0..1  (m half)
    const int wc   = q & 3;             // 0..3  (n quarter)
    const int n0   = blockIdx.x * 256;  // N-tile base (out column)
    const int by   = blockIdx.y;        // k-split 0..33

    const float sv  = __ldg(s_ptr);
    const float a   = 0.2f / (1.0f + expf(-sv));
    const float oma = 1.0f - a;

    const int C = (by < 32) ? 128 : 34; // chunks of K=32

    // ---------- producer: fill stage for chunk c ----------
    auto fill = [&](int c) {
        const int st = c & (STAGES - 1);
        const uint32_t aS = aB + st * A_ST;
        const uint32_t bS = bB + st * B_ST;

        const float* bsrc; int bstride; int bcol;
        const float* asrc = x; int astr = 1024; int acol = 0; float asc = a;
        bool isY = false; int xi = 0, zc0 = 0;
        if (by < 32) {
            const int gk = by * 4096 + c * 32;
            bsrc = dw_W; bstride = 131072; bcol = gk;
            isY = true; xi = gk >> 7; zc0 = gk & 127;
        } else {
            const int ke = (by - 32) * 1088 + c * 32;
            if (ke < 1024)      { bsrc = base_w; bstride = 1024; bcol = ke;
                                  asrc = x; astr = 1024; acol = ke;        asc = a;   }
            else if (ke < 2048) { bsrc = dw_b;   bstride = 1024; bcol = ke - 1024;
                                  asrc = x; astr = 1024; acol = ke - 1024; asc = oma; }
            else                { bsrc = db_W;   bstride = 128;  bcol = ke - 2048;
                                  asrc = z; astr = 128;  acol = ke - 2048; asc = oma; }
        }

        // B: 256 rows x 128B via cp.async into 144B-padded rows (8 ops/thread)
        #pragma unroll
        for (int j = 0; j < 8; j++) {
            const int lin = tid + j * THREADS;
            const int n = lin >> 3, sub = lin & 7;
            const float* src = bsrc + (size_t)(n0 + n) * bstride + bcol + sub * 4;
            CPA16(bS + n * 144 + sub * 16, src);
        }

        // A: fragment-major, warp q produces m-rows [16q, 16q+16)
        const int m0 = q * 16 + gid, m1 = m0 + 8;
        const uint32_t aW = aS + q * 2048 + lane * 16;
        if (isY) {
            const float xs0 = oma * __ldg(x + m0 * 1024 + xi);
            const float xs1 = oma * __ldg(x + m1 * 1024 + xi);
            #pragma unroll
            for (int ks = 0; ks < 4; ks++) {
                const int za = zc0 + ks * 8 + tig;
                const float z0a = __ldg(z + m0 * 128 + za);
                const float z1a = __ldg(z + m1 * 128 + za);
                const float z0b = __ldg(z + m0 * 128 + za + 4);
                const float z1b = __ldg(z + m1 * 128 + za + 4);
                STS128(aW + ks * 512, rna(xs0 * z0a), rna(xs1 * z1a),
                                      rna(xs0 * z0b), rna(xs1 * z1b));
            }
        } else {
            #pragma unroll
            for (int ks = 0; ks < 4; ks++) {
                const int ka = acol + ks * 8 + tig;
                const float v0 = asc * __ldg(asrc + m0 * astr + ka);
                const float v1 = asc * __ldg(asrc + m1 * astr + ka);
                const float v2 = asc * __ldg(asrc + m0 * astr + ka + 4);
                const float v3 = asc * __ldg(asrc + m1 * astr + ka + 4);
                STS128(aW + ks * 512, rna(v0), rna(v1), rna(v2), rna(v3));
            }
        }
        CPA_COMMIT();
    };

    float acc[4][8][4];
    #pragma unroll
    for (int mt = 0; mt < 4; mt++)
        #pragma unroll
        for (int nt = 0; nt < 8; nt++)
            #pragma unroll
            for (int r = 0; r < 4; r++) acc[mt][nt][r] = 0.0f;

    for (int c = 0; c < STAGES; c++) fill(c);

    for (int c = 0; c < C; c++) {
        const int rem = C - 1 - c;
        if (rem >= 3)      CPA_WAIT(3);
        else if (rem == 2) CPA_WAIT(2);
        else if (rem == 1) CPA_WAIT(1);
        else               CPA_WAIT(0);
        __syncthreads();

        const int st = c & (STAGES - 1);
        const uint32_t aS = aB + st * A_ST + wr * 8192 + lane * 16;
        const uint32_t bS = bB + st * B_ST + (wc * 64 + gid) * 144 + tig * 4;
        #pragma unroll
        for (int ks = 0; ks < 4; ks++) {
            uint32_t af[4][4];
            #pragma unroll
            for (int mt = 0; mt < 4; mt++)
                LDS128(af[mt][0], af[mt][1], af[mt][2], af[mt][3],
                       aS + mt * 2048 + ks * 512);
            uint32_t bf[8][2];
            #pragma unroll
            for (int nt = 0; nt < 8; nt++) {
                const uint32_t ba = bS + nt * (8 * 144) + ks * 32;
                LDS32(bf[nt][0], ba);
                LDS32(bf[nt][1], ba + 16);
                bf[nt][0] += 0x1000u;          // round fp32 -> tf32 (half-up)
                bf[nt][1] += 0x1000u;
            }
            #pragma unroll
            for (int mt = 0; mt < 4; mt++)
                #pragma unroll
                for (int nt = 0; nt < 8; nt++)
                    MMA(acc[mt][nt], af[mt], bf[nt]);
        }
        __syncthreads();
        if (c + STAGES < C) fill(c + STAGES);
    }

    // ---------- epilogue: write partials ----------
    float* dst = g_scratch[by];
    #pragma unroll
    for (int mt = 0; mt < 4; mt++) {
        const int m = wr * 64 + mt * 16 + gid;
        #pragma unroll
        for (int nt = 0; nt < 8; nt++) {
            const int n = n0 + wc * 64 + nt * 8 + tig * 2;
            float2 v0; v0.x = acc[mt][nt][0]; v0.y = acc[mt][nt][1];
            float2 v1; v1.x = acc[mt][nt][2]; v1.y = acc[mt][nt][3];
            *(float2*)(dst + (size_t)m * OUT_DIM + n) = v0;
            *(float2*)(dst + (size_t)(m + 8) * OUT_DIM + n) = v1;
        }
    }
}

// ---------- reduce: sum 34 partials + bias terms ----------
__global__ void __launch_bounds__(256)
hyper_reduce(const float* __restrict__ base_bias, const float* __restrict__ db_b,
             const float* __restrict__ s_ptr, float* __restrict__ out)
{
    const int idx = blockIdx.x * 256 + threadIdx.x;   // 0..131071
    const float sv = __ldg(s_ptr);
    const float a = 0.2f / (1.0f + expf(-sv));
    const int o = idx & (OUT_DIM - 1);
    float acc = a * base_bias[o] + (1.0f - a) * db_b[o];
    #pragma unroll
    for (int k = 0; k < 34; k++) acc += g_scratch[k][idx];
    out[idx] = acc;
}

// ---------- launch ----------
extern "C" void kernel_launch(void* const* d_in, const int* in_sizes, int n_in,
                              void* d_out, int out_size) {
    const float* x      = (const float*)d_in[0];
    const float* z      = (const float*)d_in[1];
    const float* base_w = (const float*)d_in[2];
    const float* dw_W   = (const float*)d_in[3];
    const float* dw_b   = (const float*)d_in[4];
    const float* base_b = (const float*)d_in[5];
    const float* db_W   = (const float*)d_in[6];
    const float* db_b   = (const float*)d_in[7];
    const float* s      = (const float*)d_in[8];

    cudaFuncSetAttribute(hyper_gemm, cudaFuncAttributeMaxDynamicSharedMemorySize, SMEM_TOTAL);

    hyper_gemm<<<dim3(4, 34), THREADS, SMEM_TOTAL>>>(x, z, base_w, dw_W, dw_b, db_W, s);
    hyper_reduce<<<(B_DIM * OUT_DIM) / 256, 256>>>(base_b, db_b, s, (float*)d_out);
}

// round 14
// speedup vs baseline: 1.2698x; 1.2698x over previous
// HyperGatedLinear — mma.sync fp16 m16n8k16 (sm_103 plain target; tcgen05 unavailable).
// out[b,o] = a·(x·bw^T) + (1-a)·(Y·dwW_view^T) + (1-a)·(x·dwb_view^T)
//          + (1-a)·(z·dbW^T) + a·bb[o] + (1-a)·dbb[o],
// Y[b, i*128+zc] = x[b,i]·z[b,zc]; dw_W viewed [OUT, IN*ZD] is K-major contiguous.
#include <cuda_runtime.h>
#include <cstdint>
#include <math.h>

#define B_DIM    128
#define OUT_DIM  1024
#define THREADS  256
#define STAGES   4
#define A_ST     8192           // 128 m x 32 k fp16, fragment-major
#define B_ST     36864          // 256 n rows x 36 floats (144 B padded)
#define SMEM_TOTAL (STAGES * (A_ST + B_ST))   // 180224 B

__device__ float g_scratch[34][B_DIM * OUT_DIM];

// ---------- helpers ----------
static __device__ __forceinline__ uint32_t smem_u32(const void* p) {
    uint32_t r;
    asm("{ .reg .u64 t; cvta.to.shared.u64 t, %1; cvt.u32.u64 %0, t; }" : "=r"(r) : "l"(p));
    return r;
}
// pack two fp32 -> f16x2 reg (lo = first arg, hi = second)
static __device__ __forceinline__ uint32_t pack2(float lo, float hi) {
    uint32_t d; asm("cvt.rn.f16x2.f32 %0, %1, %2;" : "=r"(d) : "f"(hi), "f"(lo)); return d;
}
#define CPA16(dst, src) asm volatile("cp.async.cg.shared.global [%0], [%1], 16;" :: "r"(dst), "l"(src) : "memory")
#define CPA_COMMIT()    asm volatile("cp.async.commit_group;" ::: "memory")
#define CPA_WAIT(n)     asm volatile("cp.async.wait_group %0;" :: "n"(n) : "memory")
#define STS128(a, r0, r1, r2, r3) \
    asm volatile("st.shared.v4.b32 [%0], {%1,%2,%3,%4};" :: "r"(a), "r"(r0), "r"(r1), "r"(r2), "r"(r3) : "memory")
#define LDS128(r0, r1, r2, r3, a) \
    asm volatile("ld.shared.v4.b32 {%0,%1,%2,%3}, [%4];" : "=r"(r0), "=r"(r1), "=r"(r2), "=r"(r3) : "r"(a))
#define LDS64F(f0, f1, a) \
    asm volatile("ld.shared.v2.f32 {%0,%1}, [%2];" : "=f"(f0), "=f"(f1) : "r"(a))

#define MMA16(c, aa, bb)                                                        \
    asm volatile(                                                               \
        "mma.sync.aligned.m16n8k16.row.col.f32.f16.f16.f32 "                    \
        "{%0,%1,%2,%3}, {%4,%5,%6,%7}, {%8,%9}, {%0,%1,%2,%3};"                 \
        : "+f"((c)[0]), "+f"((c)[1]), "+f"((c)[2]), "+f"((c)[3])                \
        : "r"((aa)[0]), "r"((aa)[1]), "r"((aa)[2]), "r"((aa)[3]),               \
          "r"((bb)[0]), "r"((bb)[1]))

// ---------- GEMM kernel: grid (4 N-tiles, 34 K-splits), 256 threads ----------
__global__ void __launch_bounds__(THREADS, 1)
hyper_gemm(const float* __restrict__ x, const float* __restrict__ z,
           const float* __restrict__ base_w, const float* __restrict__ dw_W,
           const float* __restrict__ dw_b, const float* __restrict__ db_W,
           const float* __restrict__ s_ptr)
{
    extern __shared__ char smem[];
    const uint32_t sb = smem_u32(smem);
    const uint32_t aB = sb;
    const uint32_t bB = sb + STAGES * A_ST;

    const int tid  = threadIdx.x;
    const int lane = tid & 31;
    const int q    = tid >> 5;          // warp id 0..7
    const int gid  = lane >> 2;         // 0..7
    const int tig  = lane & 3;          // 0..3
    const int wr   = q >> 2;            // 0..1  (m half)
    const int wc   = q & 3;             // 0..3  (n quarter)
    const int n0   = blockIdx.x * 256;  // N-tile base (out column)
    const int by   = blockIdx.y;        // k-split 0..33

    const float sv  = __ldg(s_ptr);
    const float a   = 0.2f / (1.0f + expf(-sv));
    const float oma = 1.0f - a;

    const int C = (by < 32) ? 128 : 34; // chunks of K=32

    // ---------- producer: fill stage for chunk c ----------
    auto fill = [&](int c) {
        const int st = c & (STAGES - 1);
        const uint32_t aS = aB + st * A_ST;
        const uint32_t bS = bB + st * B_ST;

        const float* bsrc; int bstride; int bcol;
        const float* asrc = x; int astr = 1024; int acol = 0; float asc = a;
        bool isY = false; int xi = 0, zc0 = 0;
        if (by < 32) {
            const int gk = by * 4096 + c * 32;
            bsrc = dw_W; bstride = 131072; bcol = gk;
            isY = true; xi = gk >> 7; zc0 = gk & 127;
        } else {
            const int ke = (by - 32) * 1088 + c * 32;
            if (ke < 1024)      { bsrc = base_w; bstride = 1024; bcol = ke;
                                  asrc = x; astr = 1024; acol = ke;        asc = a;   }
            else if (ke < 2048) { bsrc = dw_b;   bstride = 1024; bcol = ke - 1024;
                                  asrc = x; astr = 1024; acol = ke - 1024; asc = oma; }
            else                { bsrc = db_W;   bstride = 128;  bcol = ke - 2048;
                                  asrc = z; astr = 128;  acol = ke - 2048; asc = oma; }
        }

        // B: 256 rows x 128B fp32 via cp.async into 144B-padded rows (8 ops/thread)
        #pragma unroll
        for (int j = 0; j < 8; j++) {
            const int lin = tid + j * THREADS;
            const int n = lin >> 3, sub = lin & 7;
            const float* src = bsrc + (size_t)(n0 + n) * bstride + bcol + sub * 4;
            CPA16(bS + n * 144 + sub * 16, src);
        }

        // A: fp16 fragment-major; warp q produces m-rows [16q, 16q+16)
        const int m0 = q * 16 + gid, m1 = m0 + 8;
        const uint32_t aW = aS + q * 1024 + lane * 16;
        if (isY) {
            const float xs0 = oma * __ldg(x + m0 * 1024 + xi);
            const float xs1 = oma * __ldg(x + m1 * 1024 + xi);
            #pragma unroll
            for (int s = 0; s < 2; s++) {
                const int k = zc0 + s * 16 + 2 * tig;
                const float2 p00 = *(const float2*)(z + m0 * 128 + k);
                const float2 p10 = *(const float2*)(z + m1 * 128 + k);
                const float2 p01 = *(const float2*)(z + m0 * 128 + k + 8);
                const float2 p11 = *(const float2*)(z + m1 * 128 + k + 8);
                STS128(aW + s * 512,
                       pack2(xs0 * p00.x, xs0 * p00.y),
                       pack2(xs1 * p10.x, xs1 * p10.y),
                       pack2(xs0 * p01.x, xs0 * p01.y),
                       pack2(xs1 * p11.x, xs1 * p11.y));
            }
        } else {
            #pragma unroll
            for (int s = 0; s < 2; s++) {
                const int k = acol + s * 16 + 2 * tig;
                const float2 p00 = *(const float2*)(asrc + m0 * astr + k);
                const float2 p10 = *(const float2*)(asrc + m1 * astr + k);
                const float2 p01 = *(const float2*)(asrc + m0 * astr + k + 8);
                const float2 p11 = *(const float2*)(asrc + m1 * astr + k + 8);
                STS128(aW + s * 512,
                       pack2(asc * p00.x, asc * p00.y),
                       pack2(asc * p10.x, asc * p10.y),
                       pack2(asc * p01.x, asc * p01.y),
                       pack2(asc * p11.x, asc * p11.y));
            }
        }
        CPA_COMMIT();
    };

    float acc[4][8][4];
    #pragma unroll
    for (int mt = 0; mt < 4; mt++)
        #pragma unroll
        for (int nt = 0; nt < 8; nt++)
            #pragma unroll
            for (int r = 0; r < 4; r++) acc[mt][nt][r] = 0.0f;

    for (int c = 0; c < STAGES; c++) fill(c);

    for (int c = 0; c < C; c++) {
        const int rem = C - 1 - c;
        if (rem >= 3)      CPA_WAIT(3);
        else if (rem == 2) CPA_WAIT(2);
        else if (rem == 1) CPA_WAIT(1);
        else               CPA_WAIT(0);
        __syncthreads();

        const int st = c & (STAGES - 1);
        const uint32_t aS = aB + st * A_ST + wr * 4096 + lane * 16;
        const uint32_t bS = bB + st * B_ST + (wc * 64 + gid) * 144 + tig * 8;
        #pragma unroll
        for (int s = 0; s < 2; s++) {
            uint32_t af[4][4];
            #pragma unroll
            for (int mt = 0; mt < 4; mt++)
                LDS128(af[mt][0], af[mt][1], af[mt][2], af[mt][3],
                       aS + mt * 1024 + s * 512);
            uint32_t bf[8][2];
            #pragma unroll
            for (int nt = 0; nt < 8; nt++) {
                const uint32_t ba = bS + nt * (8 * 144) + s * 64;
                float lo0, lo1, hi0, hi1;
                LDS64F(lo0, lo1, ba);          // k = 2tig, 2tig+1
                LDS64F(hi0, hi1, ba + 32);     // k = 2tig+8, 2tig+9
                bf[nt][0] = pack2(lo0, lo1);
                bf[nt][1] = pack2(hi0, hi1);
            }
            #pragma unroll
            for (int mt = 0; mt < 4; mt++)
                #pragma unroll
                for (int nt = 0; nt < 8; nt++)
                    MMA16(acc[mt][nt], af[mt], bf[nt]);
        }
        __syncthreads();
        if (c + STAGES < C) fill(c + STAGES);
    }

    // ---------- epilogue: write partials ----------
    float* dst = g_scratch[by];
    #pragma unroll
    for (int mt = 0; mt < 4; mt++) {
        const int m = wr * 64 + mt * 16 + gid;
        #pragma unroll
        for (int nt = 0; nt < 8; nt++) {
            const int n = n0 + wc * 64 + nt * 8 + tig * 2;
            float2 v0; v0.x = acc[mt][nt][0]; v0.y = acc[mt][nt][1];
            float2 v1; v1.x = acc[mt][nt][2]; v1.y = acc[mt][nt][3];
            *(float2*)(dst + (size_t)m * OUT_DIM + n) = v0;
            *(float2*)(dst + (size_t)(m + 8) * OUT_DIM + n) = v1;
        }
    }
}

// ---------- reduce: sum 34 partials + bias terms ----------
__global__ void __launch_bounds__(256)
hyper_reduce(const float* __restrict__ base_bias, const float* __restrict__ db_b,
             const float* __restrict__ s_ptr, float* __restrict__ out)
{
    const int idx = blockIdx.x * 256 + threadIdx.x;   // 0..131071
    const float sv = __ldg(s_ptr);
    const float a = 0.2f / (1.0f + expf(-sv));
    const int o = idx & (OUT_DIM - 1);
    float acc = a * base_bias[o] + (1.0f - a) * db_b[o];
    #pragma unroll
    for (int k = 0; k < 34; k++) acc += g_scratch[k][idx];
    out[idx] = acc;
}

// ---------- launch ----------
extern "C" void kernel_launch(void* const* d_in, const int* in_sizes, int n_in,
                              void* d_out, int out_size) {
    const float* x      = (const float*)d_in[0];
    const float* z      = (const float*)d_in[1];
    const float* base_w = (const float*)d_in[2];
    const float* dw_W   = (const float*)d_in[3];
    const float* dw_b   = (const float*)d_in[4];
    const float* base_b = (const float*)d_in[5];
    const float* db_W   = (const float*)d_in[6];
    const float* db_b   = (const float*)d_in[7];
    const float* s      = (const float*)d_in[8];

    cudaFuncSetAttribute(hyper_gemm, cudaFuncAttributeMaxDynamicSharedMemorySize, SMEM_TOTAL);

    hyper_gemm<<<dim3(4, 34), THREADS, SMEM_TOTAL>>>(x, z, base_w, dw_W, dw_b, db_W, s);
    hyper_reduce<<<(B_DIM * OUT_DIM) / 256, 256>>>(base_b, db_b, s, (float*)d_out);
}